// round 11
// baseline (speedup 1.0000x reference)
#include <cuda_runtime.h>
#include <cuda_bf16.h>
#include <cstdint>
#include <math.h>

static constexpr int BB = 65536;
static constexpr int DD = 64;
static constexpr int HH = 512;

// ---------------- scratch (__device__ globals; allocation-free rule) -------------
// int16 fixed-point tensors stored as two s8 planes: q = qh*256 + ql (centered split)
__device__ __align__(16) int8_t g_xh[(size_t)BB * DD],  g_xl[(size_t)BB * DD];
__device__ __align__(16) int8_t g_h0h[(size_t)BB * HH], g_h0l[(size_t)BB * HH];
__device__ __align__(16) int8_t g_h1h[(size_t)BB * HH], g_h1l[(size_t)BB * HH];
__device__ __align__(16) int8_t g_dah[(size_t)BB * HH], g_dal[(size_t)BB * HH];   // d2 then d0
__device__ __align__(16) int8_t g_d1h[(size_t)BB * HH], g_d1l[(size_t)BB * HH];
// Weight planes. Forward needs W^T ([N,K] K-major); backward needs W direct ([N,K]).
__device__ __align__(16) int8_t g_W0Th[HH * DD], g_W0Tl[HH * DD];   // [512,64]
__device__ __align__(16) int8_t g_W1Th[HH * HH], g_W1Tl[HH * HH];
__device__ __align__(16) int8_t g_W2Th[HH * HH], g_W2Tl[HH * HH];
__device__ __align__(16) int8_t g_W1h[HH * HH],  g_W1l[HH * HH];
__device__ __align__(16) int8_t g_W2h[HH * HH],  g_W2l[HH * HH];
__device__ __align__(16) int8_t g_W0h[DD * HH],  g_W0l[DD * HH];    // [64,512]

// ---------------- quantization scales (compile-time, derived from problem spec) ----
// |x| <= ~5.2 (N(0,1), 4.2M samples) -> range 6.6
// |h| < 1 (tanh), |W0| <= 1/8, |W1|,|W2|,|W3| <= 1/sqrt(512)=0.04419
// |d2| <= |W3| <= 0.0442; d1 rms ~0.012 (range 0.16 = 2.4x max); d0 rms ~0.0054 (range 0.08)
static constexpr float S_x  = 4900.0f;
static constexpr float S_h  = 32000.0f;
static constexpr float S_W0 = 256000.0f;
static constexpr float S_W  = 720000.0f;
static constexpr float S_d2 = 700000.0f;
static constexpr float S_d1 = 200000.0f;
static constexpr float S_d0 = 400000.0f;

// ---------------- helpers (all base-target PTX: sm_80-era) ----------------
__device__ __forceinline__ uint32_t smem_u32(const void* p) {
    uint32_t a;
    asm("{ .reg .u64 t; cvta.to.shared.u64 t, %1; cvt.u32.u64 %0, t; }" : "=r"(a) : "l"(p));
    return a;
}
__device__ __forceinline__ void cp16(uint32_t s, const void* g) {
    asm volatile("cp.async.cg.shared.global [%0], [%1], 16;" :: "r"(s), "l"(g));
}
#define CP_COMMIT() asm volatile("cp.async.commit_group;" ::: "memory")
#define CP_WAIT1()  asm volatile("cp.async.wait_group 1;" ::: "memory")
#define CP_WAIT0()  asm volatile("cp.async.wait_group 0;" ::: "memory")

#define LDSM4(R, addr)                                                                   \
    asm volatile("ldmatrix.sync.aligned.m8n8.x4.shared.b16 {%0,%1,%2,%3}, [%4];"         \
        : "=r"((R)[0]), "=r"((R)[1]), "=r"((R)[2]), "=r"((R)[3]) : "r"(addr))

// s8 IMMA, s32 accumulate (exact)
#define IMMA(C, A, b0_, b1_)                                                             \
    asm volatile("mma.sync.aligned.m16n8k32.row.col.s32.s8.s8.s32 "                      \
        "{%0,%1,%2,%3},{%4,%5,%6,%7},{%8,%9},{%0,%1,%2,%3};"                             \
        : "+r"((C)[0]), "+r"((C)[1]), "+r"((C)[2]), "+r"((C)[3])                         \
        : "r"((A)[0]), "r"((A)[1]), "r"((A)[2]), "r"((A)[3]), "r"(b0_), "r"(b1_))

__device__ __forceinline__ float tanh_fast(float x) {
    float e = __expf(2.0f * x);
    return 1.0f - __fdividef(2.0f, e + 1.0f);
}
__device__ __forceinline__ float sech2_of(float z) {   // 1 - tanh(z)^2
    float e = __expf(2.0f * z);
    float s = __fdividef(2.0f, e + 1.0f);              // s = 1 - tanh
    return s * (2.0f - s);
}
// quantize two fp32 values -> packed u16 (hi-plane byte pair, lo-plane byte pair)
__device__ __forceinline__ void quant2(float a, float b, float S,
                                       uint16_t& hw, uint16_t& lw) {
    int qa = __float2int_rn(a * S); qa = max(-32600, min(32600, qa));
    int qb = __float2int_rn(b * S); qb = max(-32600, min(32600, qb));
    int qah = (qa + 128) >> 8, qal = qa - (qah << 8);
    int qbh = (qb + 128) >> 8, qbl = qb - (qbh << 8);
    hw = (uint16_t)((qah & 0xFF) | ((qbh & 0xFF) << 8));
    lw = (uint16_t)((qal & 0xFF) | ((qbl & 0xFF) << 8));
}

// ---------------- prep kernels: fp32 -> (hi,lo) s8 planes ----------------
__global__ void quant_direct(const float* __restrict__ src, int8_t* __restrict__ qh,
                             int8_t* __restrict__ ql, float S, int n) {
    int i = blockIdx.x * blockDim.x + threadIdx.x;
    if (i < n) {
        int q = __float2int_rn(src[i] * S);
        q = max(-32600, min(32600, q));
        int h = (q + 128) >> 8;
        qh[i] = (int8_t)h;
        ql[i] = (int8_t)(q - (h << 8));
    }
}
__global__ void quant_trans(const float* __restrict__ src, int8_t* __restrict__ qh,
                            int8_t* __restrict__ ql, float S, int R, int C) {
    int i = blockIdx.x * blockDim.x + threadIdx.x;
    if (i < R * C) {
        int r = i / C, c = i % C;
        int q = __float2int_rn(src[i] * S);
        q = max(-32600, min(32600, q));
        int h = (q + 128) >> 8;
        qh[(size_t)c * R + r] = (int8_t)h;
        ql[(size_t)c * R + r] = (int8_t)(q - (h << 8));
    }
}

// ---------------- stage loader: 64 s8 of K per row (64B data + 16B pad) -----------
template<int BN>
__device__ __forceinline__ void load_stage(
    uint32_t base_u, int buf,
    const int8_t* __restrict__ Ah, const int8_t* __restrict__ Al,
    const int8_t* __restrict__ Bh, const int8_t* __restrict__ Bl,
    int bm, int bn, int K, int k0, int tid)
{
    constexpr int ASZ = 128 * 80;
    constexpr int BSZ = BN * 80;
    constexpr int STAGE = 2 * ASZ + 2 * BSZ;
    uint32_t sb = base_u + (uint32_t)(buf * STAGE);
#pragma unroll
    for (int i = tid; i < 128 * 4; i += 256) {
        int r = i >> 2, cc = i & 3;
        size_t go = (size_t)(bm + r) * K + k0 + cc * 16;
        uint32_t so = sb + (uint32_t)(r * 80 + cc * 16);
        cp16(so, Ah + go);
        cp16(so + ASZ, Al + go);
    }
#pragma unroll
    for (int i = tid; i < BN * 4; i += 256) {
        int r = i >> 2, cc = i & 3;
        size_t go = (size_t)(bn + r) * K + k0 + cc * 16;
        uint32_t so = sb + (uint32_t)(2 * ASZ + r * 80 + cc * 16);
        cp16(so, Bh + go);
        cp16(so + BSZ, Bl + go);
    }
}

// ---------------- fused split-s8 IMMA GEMM ----------------
// q-dot: acc = HH*2^16 + (HL+LH)*2^8  (ll dropped: zero-mean, ~1e-4 rel)
// MODE 0: h = tanh(v + bias[n])               -> s8 planes (Sout)
// MODE 1: out = w3[n]*(1 - tanh^2(v+bias[n])) -> s8 planes (Sout)
// MODE 2: g = dequant(Gh,Gl); out = v*(1-g^2) -> s8 planes (Sout)
// MODE 3: symplectic fp32 write               -> Of [B,64]
template<int MODE, int BN, int WARPS_M>
__global__ void __launch_bounds__(256)
hnn_imma(const int8_t* __restrict__ Ah, const int8_t* __restrict__ Al,
         const int8_t* __restrict__ Bh, const int8_t* __restrict__ Bl,
         const float* __restrict__ bias, const float* __restrict__ w3,
         const int8_t* __restrict__ Gh, const int8_t* __restrict__ Gl,
         int8_t* __restrict__ Oh, int8_t* __restrict__ Ol,
         float* __restrict__ Of, int K,
         float inv, float Sout, float invSg)
{
    constexpr int WARPS_N = 8 / WARPS_M;
    constexpr int WM = 128 / WARPS_M;          // 32 (BN=128) or 16 (BN=64)
    constexpr int WN = BN / WARPS_N;           // 64
    constexpr int MI = WM / 16;                // 2 or 1
    constexpr int NI = WN / 8;                 // 8
    constexpr int ASZ = 128 * 80;
    constexpr int BSZ = BN * 80;
    constexpr int STAGE = 2 * ASZ + 2 * BSZ;

    extern __shared__ char sm[];
    const uint32_t base_u = smem_u32(sm);
    const int tid = threadIdx.x;
    const int lane = tid & 31;
    const int wid = tid >> 5;
    const int wm = wid % WARPS_M;
    const int wn = wid / WARPS_M;
    const int bm = blockIdx.y * 128;
    const int bn = blockIdx.x * BN;
    const int NK = K >> 6;                     // 64 K-elems per stage

    int32_t aHH[MI][NI][4], aM[MI][NI][4];
#pragma unroll
    for (int mi = 0; mi < MI; mi++)
#pragma unroll
        for (int ni = 0; ni < NI; ni++)
#pragma unroll
            for (int r = 0; r < 4; r++) { aHH[mi][ni][r] = 0; aM[mi][ni][r] = 0; }

    load_stage<BN>(base_u, 0, Ah, Al, Bh, Bl, bm, bn, K, 0, tid);
    CP_COMMIT();

    for (int ks = 0; ks < NK; ks++) {
        if (ks + 1 < NK) {
            load_stage<BN>(base_u, (ks + 1) & 1, Ah, Al, Bh, Bl, bm, bn, K, (ks + 1) << 6, tid);
            CP_COMMIT();
            CP_WAIT1();
        } else {
            CP_WAIT0();
        }
        __syncthreads();

        const uint32_t sb = base_u + (uint32_t)((ks & 1) * STAGE);
#pragma unroll
        for (int kk = 0; kk < 2; kk++) {       // two k32 sub-steps per 64-deep stage
            const int kbyte = kk * 32;
            uint32_t afh[MI][4], afl[MI][4];
#pragma unroll
            for (int mi = 0; mi < MI; mi++) {
                uint32_t addr = sb + (uint32_t)((wm * WM + mi * 16 + (lane & 15)) * 80 +
                                                kbyte + (lane >> 4) * 16);
                LDSM4(afh[mi], addr);
                LDSM4(afl[mi], addr + ASZ);
            }
#pragma unroll
            for (int n2 = 0; n2 < NI / 2; n2++) {
                uint32_t baddr = sb + (uint32_t)(2 * ASZ +
                    (wn * WN + n2 * 16 + ((lane >> 4) << 3) + (lane & 7)) * 80 +
                    kbyte + ((lane >> 3) & 1) * 16);
                uint32_t bfh[4], bfl[4];
                LDSM4(bfh, baddr);
                LDSM4(bfl, baddr + BSZ);
#pragma unroll
                for (int mi = 0; mi < MI; mi++) {
                    IMMA(aHH[mi][2 * n2],     afh[mi], bfh[0], bfh[1]);
                    IMMA(aHH[mi][2 * n2 + 1], afh[mi], bfh[2], bfh[3]);
                    IMMA(aM[mi][2 * n2],      afh[mi], bfl[0], bfl[1]);
                    IMMA(aM[mi][2 * n2 + 1],  afh[mi], bfl[2], bfl[3]);
                    IMMA(aM[mi][2 * n2],      afl[mi], bfh[0], bfh[1]);
                    IMMA(aM[mi][2 * n2 + 1],  afl[mi], bfh[2], bfh[3]);
                }
            }
        }
        __syncthreads();
    }

    // -------- fused epilogue --------
#pragma unroll
    for (int mi = 0; mi < MI; mi++) {
#pragma unroll
        for (int ni = 0; ni < NI; ni++) {
            // exact int16 dot reconstruction (all terms < 2^24, conversions exact)
            float c0 = ((float)aHH[mi][ni][0] * 65536.f + (float)aM[mi][ni][0] * 256.f) * inv;
            float c1 = ((float)aHH[mi][ni][1] * 65536.f + (float)aM[mi][ni][1] * 256.f) * inv;
            float c2 = ((float)aHH[mi][ni][2] * 65536.f + (float)aM[mi][ni][2] * 256.f) * inv;
            float c3 = ((float)aHH[mi][ni][3] * 65536.f + (float)aM[mi][ni][3] * 256.f) * inv;
            const int gn = bn + wn * WN + ni * 8 + (lane & 3) * 2;
            const int r0 = bm + wm * WM + mi * 16 + (lane >> 2);
            const int r1 = r0 + 8;

            if (MODE == 0 || MODE == 1) {
                const float bb0 = bias[gn], bb1 = bias[gn + 1];
                float v0, v1, v2, v3;
                if (MODE == 0) {
                    v0 = tanh_fast(c0 + bb0); v1 = tanh_fast(c1 + bb1);
                    v2 = tanh_fast(c2 + bb0); v3 = tanh_fast(c3 + bb1);
                } else {
                    const float w0 = w3[gn], w1 = w3[gn + 1];
                    v0 = w0 * sech2_of(c0 + bb0); v1 = w1 * sech2_of(c1 + bb1);
                    v2 = w0 * sech2_of(c2 + bb0); v3 = w1 * sech2_of(c3 + bb1);
                }
                uint16_t hw, lw;
                quant2(v0, v1, Sout, hw, lw);
                *reinterpret_cast<uint16_t*>(Oh + (size_t)r0 * HH + gn) = hw;
                *reinterpret_cast<uint16_t*>(Ol + (size_t)r0 * HH + gn) = lw;
                quant2(v2, v3, Sout, hw, lw);
                *reinterpret_cast<uint16_t*>(Oh + (size_t)r1 * HH + gn) = hw;
                *reinterpret_cast<uint16_t*>(Ol + (size_t)r1 * HH + gn) = lw;
            } else if (MODE == 2) {
                uint16_t gh0 = *reinterpret_cast<const uint16_t*>(Gh + (size_t)r0 * HH + gn);
                uint16_t gl0 = *reinterpret_cast<const uint16_t*>(Gl + (size_t)r0 * HH + gn);
                uint16_t gh1 = *reinterpret_cast<const uint16_t*>(Gh + (size_t)r1 * HH + gn);
                uint16_t gl1 = *reinterpret_cast<const uint16_t*>(Gl + (size_t)r1 * HH + gn);
                float ga = (float)((int)(int8_t)(gh0 & 0xFF) * 256 + (int)(int8_t)(gl0 & 0xFF)) * invSg;
                float gb = (float)((int)(int8_t)(gh0 >> 8)   * 256 + (int)(int8_t)(gl0 >> 8))   * invSg;
                float gc = (float)((int)(int8_t)(gh1 & 0xFF) * 256 + (int)(int8_t)(gl1 & 0xFF)) * invSg;
                float gd = (float)((int)(int8_t)(gh1 >> 8)   * 256 + (int)(int8_t)(gl1 >> 8))   * invSg;
                float v0 = c0 * (1.0f - ga * ga), v1 = c1 * (1.0f - gb * gb);
                float v2 = c2 * (1.0f - gc * gc), v3 = c3 * (1.0f - gd * gd);
                uint16_t hw, lw;
                quant2(v0, v1, Sout, hw, lw);
                *reinterpret_cast<uint16_t*>(Oh + (size_t)r0 * HH + gn) = hw;
                *reinterpret_cast<uint16_t*>(Ol + (size_t)r0 * HH + gn) = lw;
                quant2(v2, v3, Sout, hw, lw);
                *reinterpret_cast<uint16_t*>(Oh + (size_t)r1 * HH + gn) = hw;
                *reinterpret_cast<uint16_t*>(Ol + (size_t)r1 * HH + gn) = lw;
            } else { // MODE 3: out[:,0:32] = grad[:,32:64]; out[:,32:64] = -grad[:,0:32]
                const int dc = (gn >= 32) ? gn - 32 : gn + 32;
                const float sgn = (gn >= 32) ? 1.0f : -1.0f;
                float2 t0; t0.x = sgn * c0; t0.y = sgn * c1;
                float2 t1; t1.x = sgn * c2; t1.y = sgn * c3;
                *reinterpret_cast<float2*>(Of + (size_t)r0 * DD + dc) = t0;
                *reinterpret_cast<float2*>(Of + (size_t)r1 * DD + dc) = t1;
            }
        }
    }
}

// ---------------- host ----------------
extern "C" void kernel_launch(void* const* d_in, const int* in_sizes, int n_in,
                              void* d_out, int out_size)
{
    const float* x  = (const float*)d_in[1];
    const float* W0 = (const float*)d_in[2];
    const float* b0 = (const float*)d_in[3];
    const float* W1 = (const float*)d_in[4];
    const float* b1 = (const float*)d_in[5];
    const float* W2 = (const float*)d_in[6];
    const float* b2 = (const float*)d_in[7];
    const float* W3 = (const float*)d_in[8];
    float* out = (float*)d_out;

    int8_t *xh, *xl, *h0h, *h0l, *h1h, *h1l, *dah, *dal, *d1h, *d1l;
    int8_t *W0Th, *W0Tl, *W1Th, *W1Tl, *W2Th, *W2Tl, *W1h, *W1l, *W2h, *W2l, *W0h, *W0l;
    cudaGetSymbolAddress((void**)&xh,  g_xh);   cudaGetSymbolAddress((void**)&xl,  g_xl);
    cudaGetSymbolAddress((void**)&h0h, g_h0h);  cudaGetSymbolAddress((void**)&h0l, g_h0l);
    cudaGetSymbolAddress((void**)&h1h, g_h1h);  cudaGetSymbolAddress((void**)&h1l, g_h1l);
    cudaGetSymbolAddress((void**)&dah, g_dah);  cudaGetSymbolAddress((void**)&dal, g_dal);
    cudaGetSymbolAddress((void**)&d1h, g_d1h);  cudaGetSymbolAddress((void**)&d1l, g_d1l);
    cudaGetSymbolAddress((void**)&W0Th, g_W0Th); cudaGetSymbolAddress((void**)&W0Tl, g_W0Tl);
    cudaGetSymbolAddress((void**)&W1Th, g_W1Th); cudaGetSymbolAddress((void**)&W1Tl, g_W1Tl);
    cudaGetSymbolAddress((void**)&W2Th, g_W2Th); cudaGetSymbolAddress((void**)&W2Tl, g_W2Tl);
    cudaGetSymbolAddress((void**)&W1h,  g_W1h);  cudaGetSymbolAddress((void**)&W1l,  g_W1l);
    cudaGetSymbolAddress((void**)&W2h,  g_W2h);  cudaGetSymbolAddress((void**)&W2l,  g_W2l);
    cudaGetSymbolAddress((void**)&W0h,  g_W0h);  cudaGetSymbolAddress((void**)&W0l,  g_W0l);

    // Stage: 2 A planes (128*80) + 2 B planes (BN*80); double-buffered.
    constexpr int SM128 = 2 * (2 * 128 * 80 + 2 * 128 * 80);   // 81920
    constexpr int SM64  = 2 * (2 * 128 * 80 + 2 * 64 * 80);    // 61440
    cudaFuncSetAttribute(hnn_imma<0, 128, 4>, cudaFuncAttributeMaxDynamicSharedMemorySize, SM128);
    cudaFuncSetAttribute(hnn_imma<1, 128, 4>, cudaFuncAttributeMaxDynamicSharedMemorySize, SM128);
    cudaFuncSetAttribute(hnn_imma<2, 128, 4>, cudaFuncAttributeMaxDynamicSharedMemorySize, SM128);
    cudaFuncSetAttribute(hnn_imma<3, 64, 8>,  cudaFuncAttributeMaxDynamicSharedMemorySize, SM64);

    // ---- prep: quantize/transpose operands into s8 hi/lo planes ----
    {
        int n;
        n = BB * DD; quant_direct<<<(n + 255) / 256, 256>>>(x, xh, xl, S_x, n);
        n = DD * HH; quant_direct<<<(n + 255) / 256, 256>>>(W0, W0h, W0l, S_W0, n);
        quant_trans<<<(n + 255) / 256, 256>>>(W0, W0Th, W0Tl, S_W0, DD, HH);
        n = HH * HH;
        quant_direct<<<(n + 255) / 256, 256>>>(W1, W1h, W1l, S_W, n);
        quant_direct<<<(n + 255) / 256, 256>>>(W2, W2h, W2l, S_W, n);
        quant_trans<<<(n + 255) / 256, 256>>>(W1, W1Th, W1Tl, S_W, HH, HH);
        quant_trans<<<(n + 255) / 256, 256>>>(W2, W2Th, W2Tl, S_W, HH, HH);
    }

    const dim3 gH(HH / 128, BB / 128);   // (4, 512)
    const dim3 gO(1,        BB / 128);   // (1, 512)

    // 1) h0 = tanh(x @ W0 + b0)
    hnn_imma<0, 128, 4><<<gH, 256, SM128>>>(xh, xl, W0Th, W0Tl, b0, nullptr, nullptr, nullptr,
                                            h0h, h0l, nullptr, DD,
                                            1.0f / (S_x * S_W0), S_h, 0.f);
    // 2) h1 = tanh(h0 @ W1 + b1)
    hnn_imma<0, 128, 4><<<gH, 256, SM128>>>(h0h, h0l, W1Th, W1Tl, b1, nullptr, nullptr, nullptr,
                                            h1h, h1l, nullptr, HH,
                                            1.0f / (S_h * S_W), S_h, 0.f);
    // 3) d2 = W3 * (1 - tanh^2(h1 @ W2 + b2))
    hnn_imma<1, 128, 4><<<gH, 256, SM128>>>(h1h, h1l, W2Th, W2Tl, b2, W3, nullptr, nullptr,
                                            dah, dal, nullptr, HH,
                                            1.0f / (S_h * S_W), S_d2, 0.f);
    // 4) d1 = (d2 @ W2^T) * (1 - h1^2)
    hnn_imma<2, 128, 4><<<gH, 256, SM128>>>(dah, dal, W2h, W2l, nullptr, nullptr, h1h, h1l,
                                            d1h, d1l, nullptr, HH,
                                            1.0f / (S_d2 * S_W), S_d1, 1.0f / S_h);
    // 5) d0 = (d1 @ W1^T) * (1 - h0^2)   (reuse da buffers)
    hnn_imma<2, 128, 4><<<gH, 256, SM128>>>(d1h, d1l, W1h, W1l, nullptr, nullptr, h0h, h0l,
                                            dah, dal, nullptr, HH,
                                            1.0f / (S_d1 * S_W), S_d0, 1.0f / S_h);
    // 6) out = symplectic(d0 @ W0^T)
    hnn_imma<3, 64, 8><<<gO, 256, SM64>>>(dah, dal, W0h, W0l, nullptr, nullptr, nullptr, nullptr,
                                          nullptr, nullptr, out, HH,
                                          1.0f / (S_d0 * S_W0), 0.f, 0.f);
}

// round 12
// speedup vs baseline: 2.1858x; 2.1858x over previous
#include <cuda_runtime.h>
#include <cuda_bf16.h>
#include <cstdint>
#include <math.h>

static constexpr int BB = 65536;
static constexpr int DD = 64;
static constexpr int HH = 512;

// ---------------- scratch (__device__ globals; allocation-free rule) -------------
__device__ __align__(16) __nv_bfloat16 g_xh[(size_t)BB * DD];
__device__ __align__(16) __nv_bfloat16 g_xl[(size_t)BB * DD];
__device__ __align__(16) __nv_bfloat16 g_h0h[(size_t)BB * HH];
__device__ __align__(16) __nv_bfloat16 g_h0l[(size_t)BB * HH];
__device__ __align__(16) __nv_bfloat16 g_h1h[(size_t)BB * HH];
__device__ __align__(16) __nv_bfloat16 g_h1l[(size_t)BB * HH];
__device__ __align__(16) __nv_bfloat16 g_dah[(size_t)BB * HH];   // d2, then reused for d0
__device__ __align__(16) __nv_bfloat16 g_dal[(size_t)BB * HH];
__device__ __align__(16) __nv_bfloat16 g_d1h[(size_t)BB * HH];
__device__ __align__(16) __nv_bfloat16 g_d1l[(size_t)BB * HH];
// Weight planes. Forward needs W^T ([N,K] K-major); backward needs W direct ([N,K]).
__device__ __align__(16) __nv_bfloat16 g_W0Th[HH * DD], g_W0Tl[HH * DD];   // [512,64]
__device__ __align__(16) __nv_bfloat16 g_W1Th[HH * HH], g_W1Tl[HH * HH];
__device__ __align__(16) __nv_bfloat16 g_W2Th[HH * HH], g_W2Tl[HH * HH];
__device__ __align__(16) __nv_bfloat16 g_W1h[HH * HH],  g_W1l[HH * HH];
__device__ __align__(16) __nv_bfloat16 g_W2h[HH * HH],  g_W2l[HH * HH];
__device__ __align__(16) __nv_bfloat16 g_W0h[DD * HH],  g_W0l[DD * HH];    // [64,512]

// ---------------- helpers (all base-target PTX: sm_80-era) ----------------
__device__ __forceinline__ uint32_t smem_u32(const void* p) {
    uint32_t a;
    asm("{ .reg .u64 t; cvta.to.shared.u64 t, %1; cvt.u32.u64 %0, t; }" : "=r"(a) : "l"(p));
    return a;
}
__device__ __forceinline__ void cp16(uint32_t s, const void* g) {
    asm volatile("cp.async.cg.shared.global [%0], [%1], 16;" :: "r"(s), "l"(g));
}
#define CP_COMMIT() asm volatile("cp.async.commit_group;" ::: "memory")
#define CP_WAIT2()  asm volatile("cp.async.wait_group 2;" ::: "memory")

#define LDSM4(R, addr)                                                                   \
    asm volatile("ldmatrix.sync.aligned.m8n8.x4.shared.b16 {%0,%1,%2,%3}, [%4];"         \
        : "=r"((R)[0]), "=r"((R)[1]), "=r"((R)[2]), "=r"((R)[3]) : "r"(addr))

#define MMA16816(C, A, b0_, b1_)                                                         \
    asm volatile("mma.sync.aligned.m16n8k16.row.col.f32.bf16.bf16.f32 "                  \
        "{%0,%1,%2,%3},{%4,%5,%6,%7},{%8,%9},{%0,%1,%2,%3};"                             \
        : "+f"((C)[0]), "+f"((C)[1]), "+f"((C)[2]), "+f"((C)[3])                         \
        : "r"((A)[0]), "r"((A)[1]), "r"((A)[2]), "r"((A)[3]), "r"(b0_), "r"(b1_))

__device__ __forceinline__ float tanh_fast(float x) {
    float e = __expf(2.0f * x);
    return 1.0f - __fdividef(2.0f, e + 1.0f);
}
__device__ __forceinline__ float sech2_of(float z) {   // 1 - tanh(z)^2
    float e = __expf(2.0f * z);
    float s = __fdividef(2.0f, e + 1.0f);              // s = 1 - tanh
    return s * (2.0f - s);
}
__device__ __forceinline__ void split2(float a, float b, uint32_t& hi, uint32_t& lo) {
    __nv_bfloat16 ah = __float2bfloat16(a), bh = __float2bfloat16(b);
    float ar = a - __bfloat162float(ah), br = b - __bfloat162float(bh);
    __nv_bfloat16 al = __float2bfloat16(ar), bl = __float2bfloat16(br);
    hi = (uint32_t)__bfloat16_as_ushort(ah) | ((uint32_t)__bfloat16_as_ushort(bh) << 16);
    lo = (uint32_t)__bfloat16_as_ushort(al) | ((uint32_t)__bfloat16_as_ushort(bl) << 16);
}
__device__ __forceinline__ float bflo(uint32_t u) {
    return __bfloat162float(__ushort_as_bfloat16((unsigned short)(u & 0xFFFF)));
}
__device__ __forceinline__ float bfhi(uint32_t u) {
    return __bfloat162float(__ushort_as_bfloat16((unsigned short)(u >> 16)));
}

// ---------------- prep kernels: fp32 -> (hi,lo) bf16 planes ----------------
__global__ void split_direct(const float* __restrict__ src, __nv_bfloat16* __restrict__ hi,
                             __nv_bfloat16* __restrict__ lo, int n) {
    int i = blockIdx.x * blockDim.x + threadIdx.x;
    if (i < n) {
        float v = src[i];
        __nv_bfloat16 h = __float2bfloat16(v);
        hi[i] = h;
        lo[i] = __float2bfloat16(v - __bfloat162float(h));
    }
}
__global__ void split_trans(const float* __restrict__ src, __nv_bfloat16* __restrict__ hi,
                            __nv_bfloat16* __restrict__ lo, int R, int C) {
    int i = blockIdx.x * blockDim.x + threadIdx.x;
    if (i < R * C) {
        int r = i / C, c = i % C;
        float v = src[i];
        __nv_bfloat16 h = __float2bfloat16(v);
        hi[(size_t)c * R + r] = h;
        lo[(size_t)c * R + r] = __float2bfloat16(v - __bfloat162float(h));
    }
}

// ---------------- stage loader: global -> padded smem via cp.async ----------------
// Smem rows: 32 bf16 data (64B) padded to 80B (20 words -> conflict-free ldmatrix).
template<int BN>
__device__ __forceinline__ void load_stage(
    uint32_t base_u, int buf,
    const __nv_bfloat16* __restrict__ Ah, const __nv_bfloat16* __restrict__ Al,
    const __nv_bfloat16* __restrict__ Bh, const __nv_bfloat16* __restrict__ Bl,
    int bm, int bn, int K, int k0, int tid)
{
    constexpr int ASZ = 128 * 80;
    constexpr int BSZ = BN * 80;
    constexpr int STAGE = 2 * ASZ + 2 * BSZ;
    uint32_t sb = base_u + (uint32_t)(buf * STAGE);
#pragma unroll
    for (int i = tid; i < 128 * 4; i += 256) {
        int r = i >> 2, cc = i & 3;
        size_t go = (size_t)(bm + r) * K + k0 + cc * 8;
        uint32_t so = sb + (uint32_t)(r * 80 + cc * 16);
        cp16(so, Ah + go);
        cp16(so + ASZ, Al + go);
    }
#pragma unroll
    for (int i = tid; i < BN * 4; i += 256) {
        int r = i >> 2, cc = i & 3;
        size_t go = (size_t)(bn + r) * K + k0 + cc * 8;
        uint32_t so = sb + (uint32_t)(2 * ASZ + r * 80 + cc * 16);
        cp16(so, Bh + go);
        cp16(so + BSZ, Bl + go);
    }
}

// ---------------- fused split-bf16 HMMA GEMM (4-stage, distance-2 pipeline) -------
// C[m,n] = sum_k A[m,k]*B[n,k];  A ~ Ah+Al, B ~ Bh+Bl (drop Al*Bl).
// MODE 0: h = tanh(v + bias[n])                 -> (Oh,Ol)
// MODE 1: out = w3[n]*(1 - tanh^2(v+bias[n]))   -> (Oh,Ol)
// MODE 2: g = Gh+Gl;  out = v*(1-g^2)           -> (Oh,Ol)
// MODE 3: symplectic fp32 write                 -> Of [B,64]
template<int MODE, int BN, int WARPS_M>
__global__ void __launch_bounds__(256)
hnn_mma(const __nv_bfloat16* __restrict__ Ah, const __nv_bfloat16* __restrict__ Al,
        const __nv_bfloat16* __restrict__ Bh, const __nv_bfloat16* __restrict__ Bl,
        const float* __restrict__ bias, const float* __restrict__ w3,
        const __nv_bfloat16* __restrict__ Gh, const __nv_bfloat16* __restrict__ Gl,
        __nv_bfloat16* __restrict__ Oh, __nv_bfloat16* __restrict__ Ol,
        float* __restrict__ Of, int K)
{
    constexpr int WARPS_N = 8 / WARPS_M;
    constexpr int WM = 128 / WARPS_M;          // 32 (BN=128) or 16 (BN=64)
    constexpr int WN = BN / WARPS_N;           // 64
    constexpr int MI = WM / 16;                // 2 or 1
    constexpr int NI = WN / 8;                 // 8
    constexpr int ASZ = 128 * 80;
    constexpr int BSZ = BN * 80;
    constexpr int STAGE = 2 * ASZ + 2 * BSZ;

    extern __shared__ char sm[];
    const uint32_t base_u = smem_u32(sm);
    const int tid = threadIdx.x;
    const int lane = tid & 31;
    const int wid = tid >> 5;
    const int wm = wid % WARPS_M;
    const int wn = wid / WARPS_M;
    const int bm = blockIdx.y * 128;
    const int bn = blockIdx.x * BN;
    const int NK = K >> 5;

    float acc[MI][NI][4];
#pragma unroll
    for (int mi = 0; mi < MI; mi++)
#pragma unroll
        for (int ni = 0; ni < NI; ni++)
#pragma unroll
            for (int r = 0; r < 4; r++) acc[mi][ni][r] = 0.0f;

    // prologue: prefetch stages 0 and 1 (distance 2, 4 buffers)
    load_stage<BN>(base_u, 0, Ah, Al, Bh, Bl, bm, bn, K, 0, tid);
    CP_COMMIT();
    if (NK > 1) load_stage<BN>(base_u, 1, Ah, Al, Bh, Bl, bm, bn, K, 32, tid);
    CP_COMMIT();

    for (int ks = 0; ks < NK; ks++) {
        // issue stage ks+2 (buffer safety: (ks+2)&3 == (ks-2)&3, whose compute
        // finished before the barrier of iteration ks-1 -> single barrier is safe)
        if (ks + 2 < NK)
            load_stage<BN>(base_u, (ks + 2) & 3, Ah, Al, Bh, Bl, bm, bn, K, (ks + 2) << 5, tid);
        CP_COMMIT();                 // one group per iteration (possibly empty)
        CP_WAIT2();                  // oldest pending (stage ks) complete
        __syncthreads();

        const uint32_t sb = base_u + (uint32_t)((ks & 3) * STAGE);
#pragma unroll
        for (int kk = 0; kk < 2; kk++) {
            const int kb = kk * 16;
            uint32_t afh[MI][4], afl[MI][4];
#pragma unroll
            for (int mi = 0; mi < MI; mi++) {
                uint32_t addr = sb + (uint32_t)((wm * WM + mi * 16 + (lane & 15)) * 80 +
                                                (kb + (lane >> 4) * 8) * 2);
                LDSM4(afh[mi], addr);
                LDSM4(afl[mi], addr + ASZ);
            }
#pragma unroll
            for (int n2 = 0; n2 < NI / 2; n2++) {
                uint32_t baddr = sb + (uint32_t)(2 * ASZ +
                    (wn * WN + n2 * 16 + ((lane >> 4) << 3) + (lane & 7)) * 80 +
                    (kb + ((lane >> 3) & 1) * 8) * 2);
                uint32_t bfh[4], bfl[4];
                LDSM4(bfh, baddr);
                LDSM4(bfl, baddr + BSZ);
#pragma unroll
                for (int mi = 0; mi < MI; mi++) {
                    MMA16816(acc[mi][2 * n2],     afh[mi], bfh[0], bfh[1]);
                    MMA16816(acc[mi][2 * n2 + 1], afh[mi], bfh[2], bfh[3]);
                    MMA16816(acc[mi][2 * n2],     afh[mi], bfl[0], bfl[1]);
                    MMA16816(acc[mi][2 * n2 + 1], afh[mi], bfl[2], bfl[3]);
                    MMA16816(acc[mi][2 * n2],     afl[mi], bfh[0], bfh[1]);
                    MMA16816(acc[mi][2 * n2 + 1], afl[mi], bfh[2], bfh[3]);
                }
            }
        }
        // no trailing barrier: next iteration's load targets a buffer whose
        // compute finished two iterations ago (4-buffer / distance-2 invariant)
    }

    // -------- fused epilogue --------
#pragma unroll
    for (int mi = 0; mi < MI; mi++) {
#pragma unroll
        for (int ni = 0; ni < NI; ni++) {
            float c0 = acc[mi][ni][0], c1 = acc[mi][ni][1];
            float c2 = acc[mi][ni][2], c3 = acc[mi][ni][3];
            const int gn = bn + wn * WN + ni * 8 + (lane & 3) * 2;
            const int r0 = bm + wm * WM + mi * 16 + (lane >> 2);
            const int r1 = r0 + 8;

            if (MODE == 0 || MODE == 1) {
                const float bb0 = bias[gn], bb1 = bias[gn + 1];
                float v0, v1, v2, v3;
                if (MODE == 0) {
                    v0 = tanh_fast(c0 + bb0); v1 = tanh_fast(c1 + bb1);
                    v2 = tanh_fast(c2 + bb0); v3 = tanh_fast(c3 + bb1);
                } else {
                    const float w0 = w3[gn], w1 = w3[gn + 1];
                    v0 = w0 * sech2_of(c0 + bb0); v1 = w1 * sech2_of(c1 + bb1);
                    v2 = w0 * sech2_of(c2 + bb0); v3 = w1 * sech2_of(c3 + bb1);
                }
                uint32_t hi, lo;
                split2(v0, v1, hi, lo);
                *reinterpret_cast<uint32_t*>(Oh + (size_t)r0 * HH + gn) = hi;
                *reinterpret_cast<uint32_t*>(Ol + (size_t)r0 * HH + gn) = lo;
                split2(v2, v3, hi, lo);
                *reinterpret_cast<uint32_t*>(Oh + (size_t)r1 * HH + gn) = hi;
                *reinterpret_cast<uint32_t*>(Ol + (size_t)r1 * HH + gn) = lo;
            } else if (MODE == 2) {
                uint32_t gh0 = *reinterpret_cast<const uint32_t*>(Gh + (size_t)r0 * HH + gn);
                uint32_t gl0 = *reinterpret_cast<const uint32_t*>(Gl + (size_t)r0 * HH + gn);
                uint32_t gh1 = *reinterpret_cast<const uint32_t*>(Gh + (size_t)r1 * HH + gn);
                uint32_t gl1 = *reinterpret_cast<const uint32_t*>(Gl + (size_t)r1 * HH + gn);
                float ga = bflo(gh0) + bflo(gl0), gb = bfhi(gh0) + bfhi(gl0);
                float gc = bflo(gh1) + bflo(gl1), gd = bfhi(gh1) + bfhi(gl1);
                float v0 = c0 * (1.0f - ga * ga), v1 = c1 * (1.0f - gb * gb);
                float v2 = c2 * (1.0f - gc * gc), v3 = c3 * (1.0f - gd * gd);
                uint32_t hi, lo;
                split2(v0, v1, hi, lo);
                *reinterpret_cast<uint32_t*>(Oh + (size_t)r0 * HH + gn) = hi;
                *reinterpret_cast<uint32_t*>(Ol + (size_t)r0 * HH + gn) = lo;
                split2(v2, v3, hi, lo);
                *reinterpret_cast<uint32_t*>(Oh + (size_t)r1 * HH + gn) = hi;
                *reinterpret_cast<uint32_t*>(Ol + (size_t)r1 * HH + gn) = lo;
            } else { // MODE 3: out[:,0:32] = grad[:,32:64]; out[:,32:64] = -grad[:,0:32]
                const int dc = (gn >= 32) ? gn - 32 : gn + 32;
                const float sgn = (gn >= 32) ? 1.0f : -1.0f;
                float2 t0; t0.x = sgn * c0; t0.y = sgn * c1;
                float2 t1; t1.x = sgn * c2; t1.y = sgn * c3;
                *reinterpret_cast<float2*>(Of + (size_t)r0 * DD + dc) = t0;
                *reinterpret_cast<float2*>(Of + (size_t)r1 * DD + dc) = t1;
            }
        }
    }
}

// ---------------- host ----------------
extern "C" void kernel_launch(void* const* d_in, const int* in_sizes, int n_in,
                              void* d_out, int out_size)
{
    const float* x  = (const float*)d_in[1];
    const float* W0 = (const float*)d_in[2];
    const float* b0 = (const float*)d_in[3];
    const float* W1 = (const float*)d_in[4];
    const float* b1 = (const float*)d_in[5];
    const float* W2 = (const float*)d_in[6];
    const float* b2 = (const float*)d_in[7];
    const float* W3 = (const float*)d_in[8];
    float* out = (float*)d_out;

    __nv_bfloat16 *xh, *xl, *h0h, *h0l, *h1h, *h1l, *dah, *dal, *d1h, *d1l;
    __nv_bfloat16 *W0Th, *W0Tl, *W1Th, *W1Tl, *W2Th, *W2Tl, *W1h, *W1l, *W2h, *W2l, *W0h, *W0l;
    cudaGetSymbolAddress((void**)&xh,  g_xh);   cudaGetSymbolAddress((void**)&xl,  g_xl);
    cudaGetSymbolAddress((void**)&h0h, g_h0h);  cudaGetSymbolAddress((void**)&h0l, g_h0l);
    cudaGetSymbolAddress((void**)&h1h, g_h1h);  cudaGetSymbolAddress((void**)&h1l, g_h1l);
    cudaGetSymbolAddress((void**)&dah, g_dah);  cudaGetSymbolAddress((void**)&dal, g_dal);
    cudaGetSymbolAddress((void**)&d1h, g_d1h);  cudaGetSymbolAddress((void**)&d1l, g_d1l);
    cudaGetSymbolAddress((void**)&W0Th, g_W0Th); cudaGetSymbolAddress((void**)&W0Tl, g_W0Tl);
    cudaGetSymbolAddress((void**)&W1Th, g_W1Th); cudaGetSymbolAddress((void**)&W1Tl, g_W1Tl);
    cudaGetSymbolAddress((void**)&W2Th, g_W2Th); cudaGetSymbolAddress((void**)&W2Tl, g_W2Tl);
    cudaGetSymbolAddress((void**)&W1h,  g_W1h);  cudaGetSymbolAddress((void**)&W1l,  g_W1l);
    cudaGetSymbolAddress((void**)&W2h,  g_W2h);  cudaGetSymbolAddress((void**)&W2l,  g_W2l);
    cudaGetSymbolAddress((void**)&W0h,  g_W0h);  cudaGetSymbolAddress((void**)&W0l,  g_W0l);

    // Stage bytes: 2 A planes (128*80) + 2 B planes (BN*80); 4 buffers.
    constexpr int SM128 = 4 * (2 * 128 * 80 + 2 * 128 * 80);   // 163840
    constexpr int SM64  = 4 * (2 * 128 * 80 + 2 * 64 * 80);    // 122880
    cudaFuncSetAttribute(hnn_mma<0, 128, 4>, cudaFuncAttributeMaxDynamicSharedMemorySize, SM128);
    cudaFuncSetAttribute(hnn_mma<1, 128, 4>, cudaFuncAttributeMaxDynamicSharedMemorySize, SM128);
    cudaFuncSetAttribute(hnn_mma<2, 128, 4>, cudaFuncAttributeMaxDynamicSharedMemorySize, SM128);
    cudaFuncSetAttribute(hnn_mma<3, 64, 8>,  cudaFuncAttributeMaxDynamicSharedMemorySize, SM64);

    // ---- prep: split/transpose operands into bf16 planes ----
    {
        int n;
        n = BB * DD; split_direct<<<(n + 255) / 256, 256>>>(x, xh, xl, n);
        n = DD * HH; split_direct<<<(n + 255) / 256, 256>>>(W0, W0h, W0l, n);
        split_trans<<<(n + 255) / 256, 256>>>(W0, W0Th, W0Tl, DD, HH);
        n = HH * HH;
        split_direct<<<(n + 255) / 256, 256>>>(W1, W1h, W1l, n);
        split_direct<<<(n + 255) / 256, 256>>>(W2, W2h, W2l, n);
        split_trans<<<(n + 255) / 256, 256>>>(W1, W1Th, W1Tl, HH, HH);
        split_trans<<<(n + 255) / 256, 256>>>(W2, W2Th, W2Tl, HH, HH);
    }

    const dim3 gH(HH / 128, BB / 128);   // (4, 512)
    const dim3 gO(1,        BB / 128);   // (1, 512)

    // 1) h0 = tanh(x @ W0 + b0)
    hnn_mma<0, 128, 4><<<gH, 256, SM128>>>(xh, xl, W0Th, W0Tl, b0, nullptr, nullptr, nullptr,
                                           h0h, h0l, nullptr, DD);
    // 2) h1 = tanh(h0 @ W1 + b1)
    hnn_mma<0, 128, 4><<<gH, 256, SM128>>>(h0h, h0l, W1Th, W1Tl, b1, nullptr, nullptr, nullptr,
                                           h1h, h1l, nullptr, HH);
    // 3) d2 = W3 * (1 - tanh^2(h1 @ W2 + b2))
    hnn_mma<1, 128, 4><<<gH, 256, SM128>>>(h1h, h1l, W2Th, W2Tl, b2, W3, nullptr, nullptr,
                                           dah, dal, nullptr, HH);
    // 4) d1 = (d2 @ W2^T) * (1 - h1^2)
    hnn_mma<2, 128, 4><<<gH, 256, SM128>>>(dah, dal, W2h, W2l, nullptr, nullptr, h1h, h1l,
                                           d1h, d1l, nullptr, HH);
    // 5) d0 = (d1 @ W1^T) * (1 - h0^2)   (reuse da buffers)
    hnn_mma<2, 128, 4><<<gH, 256, SM128>>>(d1h, d1l, W1h, W1l, nullptr, nullptr, h0h, h0l,
                                           dah, dal, nullptr, HH);
    // 6) out = symplectic(d0 @ W0^T)
    hnn_mma<3, 64, 8><<<gO, 256, SM64>>>(dah, dal, W0h, W0l, nullptr, nullptr, nullptr, nullptr,
                                         nullptr, nullptr, out, HH);
}

// round 13
// speedup vs baseline: 5.5681x; 2.5474x over previous
#include <cuda_runtime.h>
#include <cuda_fp16.h>
#include <cstdint>
#include <math.h>

static constexpr int BB = 65536;
static constexpr int DD = 64;
static constexpr int HH = 512;

// ---------------- scratch (__device__ globals; allocation-free rule) -------------
// single fp16 plane per tensor
__device__ __align__(16) __half g_x [(size_t)BB * DD];
__device__ __align__(16) __half g_h0[(size_t)BB * HH];
__device__ __align__(16) __half g_h1[(size_t)BB * HH];
__device__ __align__(16) __half g_da[(size_t)BB * HH];   // d2, then reused for d0
__device__ __align__(16) __half g_d1[(size_t)BB * HH];
// Weights. Forward needs W^T ([N,K] K-major); backward needs W direct ([N,K]).
__device__ __align__(16) __half g_W0T[HH * DD];          // [512,64]
__device__ __align__(16) __half g_W1T[HH * HH];
__device__ __align__(16) __half g_W2T[HH * HH];
__device__ __align__(16) __half g_W1 [HH * HH];
__device__ __align__(16) __half g_W2 [HH * HH];
__device__ __align__(16) __half g_W0 [DD * HH];          // [64,512]

// ---------------- helpers (all base-target PTX: sm_80-era) ----------------
__device__ __forceinline__ uint32_t smem_u32(const void* p) {
    uint32_t a;
    asm("{ .reg .u64 t; cvta.to.shared.u64 t, %1; cvt.u32.u64 %0, t; }" : "=r"(a) : "l"(p));
    return a;
}
__device__ __forceinline__ void cp16(uint32_t s, const void* g) {
    asm volatile("cp.async.cg.shared.global [%0], [%1], 16;" :: "r"(s), "l"(g));
}
#define CP_COMMIT() asm volatile("cp.async.commit_group;" ::: "memory")
#define CP_WAIT2()  asm volatile("cp.async.wait_group 2;" ::: "memory")

#define LDSM4(R, addr)                                                                   \
    asm volatile("ldmatrix.sync.aligned.m8n8.x4.shared.b16 {%0,%1,%2,%3}, [%4];"         \
        : "=r"((R)[0]), "=r"((R)[1]), "=r"((R)[2]), "=r"((R)[3]) : "r"(addr))

#define MMAH(C, A, b0_, b1_)                                                             \
    asm volatile("mma.sync.aligned.m16n8k16.row.col.f32.f16.f16.f32 "                    \
        "{%0,%1,%2,%3},{%4,%5,%6,%7},{%8,%9},{%0,%1,%2,%3};"                             \
        : "+f"((C)[0]), "+f"((C)[1]), "+f"((C)[2]), "+f"((C)[3])                         \
        : "r"((A)[0]), "r"((A)[1]), "r"((A)[2]), "r"((A)[3]), "r"(b0_), "r"(b1_))

__device__ __forceinline__ float tanh_fast(float x) {
    float e = __expf(2.0f * x);
    return 1.0f - __fdividef(2.0f, e + 1.0f);
}
__device__ __forceinline__ float sech2_of(float z) {   // 1 - tanh(z)^2
    float e = __expf(2.0f * z);
    float s = __fdividef(2.0f, e + 1.0f);              // s = 1 - tanh
    return s * (2.0f - s);
}
__device__ __forceinline__ uint32_t pack_h2(float a, float b) {
    __half2 h = __floats2half2_rn(a, b);
    return *reinterpret_cast<uint32_t*>(&h);
}
__device__ __forceinline__ float h2lo(uint32_t u) {
    return __half2float(__ushort_as_half((unsigned short)(u & 0xFFFF)));
}
__device__ __forceinline__ float h2hi(uint32_t u) {
    return __half2float(__ushort_as_half((unsigned short)(u >> 16)));
}

// ---------------- prep kernels: fp32 -> fp16 ----------------
__global__ void half_direct(const float* __restrict__ src, __half* __restrict__ dst, int n) {
    int i = blockIdx.x * blockDim.x + threadIdx.x;
    if (i < n) dst[i] = __float2half_rn(src[i]);
}
__global__ void half_trans(const float* __restrict__ src, __half* __restrict__ dst,
                           int R, int C) {
    int i = blockIdx.x * blockDim.x + threadIdx.x;
    if (i < R * C) {
        int r = i / C, c = i % C;
        dst[(size_t)c * R + r] = __float2half_rn(src[i]);
    }
}

// ---------------- stage loader: global -> padded smem via cp.async ----------------
// Smem rows: 32 fp16 (64B data) padded to 80B (20 words -> conflict-free ldmatrix).
template<int BN>
__device__ __forceinline__ void load_stage(
    uint32_t base_u, int buf,
    const __half* __restrict__ A, const __half* __restrict__ B,
    int bm, int bn, int K, int k0, int tid)
{
    constexpr int ASZ = 128 * 80;
    constexpr int BSZ = BN * 80;
    constexpr int STAGE = ASZ + BSZ;
    uint32_t sb = base_u + (uint32_t)(buf * STAGE);
#pragma unroll
    for (int i = tid; i < 128 * 4; i += 256) {
        int r = i >> 2, cc = i & 3;
        cp16(sb + (uint32_t)(r * 80 + cc * 16), A + (size_t)(bm + r) * K + k0 + cc * 8);
    }
#pragma unroll
    for (int i = tid; i < BN * 4; i += 256) {
        int r = i >> 2, cc = i & 3;
        cp16(sb + (uint32_t)(ASZ + r * 80 + cc * 16), B + (size_t)(bn + r) * K + k0 + cc * 8);
    }
}

// ---------------- fused fp16 HMMA GEMM (4-stage, distance-2 pipeline) -------------
// C[m,n] = sum_k A[m,k]*B[n,k], fp16 operands, fp32 accum.
// MODE 0: h = tanh(v + bias[n])                 -> O (fp16)
// MODE 1: out = w3[n]*(1 - tanh^2(v+bias[n]))   -> O (fp16)
// MODE 2: g = G[m,n]; out = v*(1-g^2)           -> O (fp16)
// MODE 3: symplectic fp32 write                 -> Of [B,64]
template<int MODE, int BN, int WARPS_M>
__global__ void __launch_bounds__(256)
hnn_mma(const __half* __restrict__ A, const __half* __restrict__ B,
        const float* __restrict__ bias, const float* __restrict__ w3,
        const __half* __restrict__ G, __half* __restrict__ O,
        float* __restrict__ Of, int K)
{
    constexpr int WARPS_N = 8 / WARPS_M;
    constexpr int WM = 128 / WARPS_M;          // 32 (BN=128) or 16 (BN=64)
    constexpr int WN = BN / WARPS_N;           // 64
    constexpr int MI = WM / 16;                // 2 or 1
    constexpr int NI = WN / 8;                 // 8
    constexpr int ASZ = 128 * 80;
    constexpr int BSZ = BN * 80;
    constexpr int STAGE = ASZ + BSZ;

    extern __shared__ char sm[];
    const uint32_t base_u = smem_u32(sm);
    const int tid = threadIdx.x;
    const int lane = tid & 31;
    const int wid = tid >> 5;
    const int wm = wid % WARPS_M;
    const int wn = wid / WARPS_M;
    const int bm = blockIdx.y * 128;
    const int bn = blockIdx.x * BN;
    const int NK = K >> 5;

    float acc[MI][NI][4];
#pragma unroll
    for (int mi = 0; mi < MI; mi++)
#pragma unroll
        for (int ni = 0; ni < NI; ni++)
#pragma unroll
            for (int r = 0; r < 4; r++) acc[mi][ni][r] = 0.0f;

    // prologue: prefetch stages 0 and 1 (distance 2, 4 buffers)
    load_stage<BN>(base_u, 0, A, B, bm, bn, K, 0, tid);
    CP_COMMIT();
    if (NK > 1) load_stage<BN>(base_u, 1, A, B, bm, bn, K, 32, tid);
    CP_COMMIT();

    for (int ks = 0; ks < NK; ks++) {
        // issue stage ks+2 (buffer (ks+2)&3 == (ks-2)&3, compute done before the
        // barrier of iteration ks-1 -> single barrier per iteration is safe)
        if (ks + 2 < NK)
            load_stage<BN>(base_u, (ks + 2) & 3, A, B, bm, bn, K, (ks + 2) << 5, tid);
        CP_COMMIT();                 // one group per iteration (possibly empty)
        CP_WAIT2();                  // oldest pending (stage ks) complete
        __syncthreads();

        const uint32_t sb = base_u + (uint32_t)((ks & 3) * STAGE);
#pragma unroll
        for (int kk = 0; kk < 2; kk++) {
            const int kb = kk * 16;
            uint32_t af[MI][4];
#pragma unroll
            for (int mi = 0; mi < MI; mi++) {
                uint32_t addr = sb + (uint32_t)((wm * WM + mi * 16 + (lane & 15)) * 80 +
                                                (kb + (lane >> 4) * 8) * 2);
                LDSM4(af[mi], addr);
            }
#pragma unroll
            for (int n2 = 0; n2 < NI / 2; n2++) {
                uint32_t baddr = sb + (uint32_t)(ASZ +
                    (wn * WN + n2 * 16 + ((lane >> 4) << 3) + (lane & 7)) * 80 +
                    (kb + ((lane >> 3) & 1) * 8) * 2);
                uint32_t bf[4];
                LDSM4(bf, baddr);
#pragma unroll
                for (int mi = 0; mi < MI; mi++) {
                    MMAH(acc[mi][2 * n2],     af[mi], bf[0], bf[1]);
                    MMAH(acc[mi][2 * n2 + 1], af[mi], bf[2], bf[3]);
                }
            }
        }
        // no trailing barrier (4-buffer / distance-2 invariant)
    }

    // -------- fused epilogue --------
#pragma unroll
    for (int mi = 0; mi < MI; mi++) {
#pragma unroll
        for (int ni = 0; ni < NI; ni++) {
            float c0 = acc[mi][ni][0], c1 = acc[mi][ni][1];
            float c2 = acc[mi][ni][2], c3 = acc[mi][ni][3];
            const int gn = bn + wn * WN + ni * 8 + (lane & 3) * 2;
            const int r0 = bm + wm * WM + mi * 16 + (lane >> 2);
            const int r1 = r0 + 8;

            if (MODE == 0 || MODE == 1) {
                const float bb0 = bias[gn], bb1 = bias[gn + 1];
                float v0, v1, v2, v3;
                if (MODE == 0) {
                    v0 = tanh_fast(c0 + bb0); v1 = tanh_fast(c1 + bb1);
                    v2 = tanh_fast(c2 + bb0); v3 = tanh_fast(c3 + bb1);
                } else {
                    const float w0 = w3[gn], w1 = w3[gn + 1];
                    v0 = w0 * sech2_of(c0 + bb0); v1 = w1 * sech2_of(c1 + bb1);
                    v2 = w0 * sech2_of(c2 + bb0); v3 = w1 * sech2_of(c3 + bb1);
                }
                *reinterpret_cast<uint32_t*>(O + (size_t)r0 * HH + gn) = pack_h2(v0, v1);
                *reinterpret_cast<uint32_t*>(O + (size_t)r1 * HH + gn) = pack_h2(v2, v3);
            } else if (MODE == 2) {
                uint32_t gw0 = *reinterpret_cast<const uint32_t*>(G + (size_t)r0 * HH + gn);
                uint32_t gw1 = *reinterpret_cast<const uint32_t*>(G + (size_t)r1 * HH + gn);
                float ga = h2lo(gw0), gb = h2hi(gw0);
                float gc = h2lo(gw1), gd = h2hi(gw1);
                float v0 = c0 * (1.0f - ga * ga), v1 = c1 * (1.0f - gb * gb);
                float v2 = c2 * (1.0f - gc * gc), v3 = c3 * (1.0f - gd * gd);
                *reinterpret_cast<uint32_t*>(O + (size_t)r0 * HH + gn) = pack_h2(v0, v1);
                *reinterpret_cast<uint32_t*>(O + (size_t)r1 * HH + gn) = pack_h2(v2, v3);
            } else { // MODE 3: out[:,0:32] = grad[:,32:64]; out[:,32:64] = -grad[:,0:32]
                const int dc = (gn >= 32) ? gn - 32 : gn + 32;
                const float sgn = (gn >= 32) ? 1.0f : -1.0f;
                float2 t0; t0.x = sgn * c0; t0.y = sgn * c1;
                float2 t1; t1.x = sgn * c2; t1.y = sgn * c3;
                *reinterpret_cast<float2*>(Of + (size_t)r0 * DD + dc) = t0;
                *reinterpret_cast<float2*>(Of + (size_t)r1 * DD + dc) = t1;
            }
        }
    }
}

// ---------------- host ----------------
extern "C" void kernel_launch(void* const* d_in, const int* in_sizes, int n_in,
                              void* d_out, int out_size)
{
    const float* x  = (const float*)d_in[1];
    const float* W0 = (const float*)d_in[2];
    const float* b0 = (const float*)d_in[3];
    const float* W1 = (const float*)d_in[4];
    const float* b1 = (const float*)d_in[5];
    const float* W2 = (const float*)d_in[6];
    const float* b2 = (const float*)d_in[7];
    const float* W3 = (const float*)d_in[8];
    float* out = (float*)d_out;

    __half *xq, *h0, *h1, *da, *d1;
    __half *W0T, *W1T, *W2T, *W1q, *W2q, *W0q;
    cudaGetSymbolAddress((void**)&xq,  g_x);
    cudaGetSymbolAddress((void**)&h0,  g_h0);
    cudaGetSymbolAddress((void**)&h1,  g_h1);
    cudaGetSymbolAddress((void**)&da,  g_da);
    cudaGetSymbolAddress((void**)&d1,  g_d1);
    cudaGetSymbolAddress((void**)&W0T, g_W0T);
    cudaGetSymbolAddress((void**)&W1T, g_W1T);
    cudaGetSymbolAddress((void**)&W2T, g_W2T);
    cudaGetSymbolAddress((void**)&W1q, g_W1);
    cudaGetSymbolAddress((void**)&W2q, g_W2);
    cudaGetSymbolAddress((void**)&W0q, g_W0);

    // Stage bytes: A (128*80) + B (BN*80); 4 buffers.
    constexpr int SM128 = 4 * (128 * 80 + 128 * 80);   // 81920 -> 2 CTAs/SM
    constexpr int SM64  = 4 * (128 * 80 + 64 * 80);    // 61440
    cudaFuncSetAttribute(hnn_mma<0, 128, 4>, cudaFuncAttributeMaxDynamicSharedMemorySize, SM128);
    cudaFuncSetAttribute(hnn_mma<1, 128, 4>, cudaFuncAttributeMaxDynamicSharedMemorySize, SM128);
    cudaFuncSetAttribute(hnn_mma<2, 128, 4>, cudaFuncAttributeMaxDynamicSharedMemorySize, SM128);
    cudaFuncSetAttribute(hnn_mma<3, 64, 8>,  cudaFuncAttributeMaxDynamicSharedMemorySize, SM64);

    // ---- prep: convert/transpose operands into fp16 ----
    {
        int n;
        n = BB * DD; half_direct<<<(n + 255) / 256, 256>>>(x, xq, n);
        n = DD * HH; half_direct<<<(n + 255) / 256, 256>>>(W0, W0q, n);
        half_trans<<<(n + 255) / 256, 256>>>(W0, W0T, DD, HH);
        n = HH * HH;
        half_direct<<<(n + 255) / 256, 256>>>(W1, W1q, n);
        half_direct<<<(n + 255) / 256, 256>>>(W2, W2q, n);
        half_trans<<<(n + 255) / 256, 256>>>(W1, W1T, HH, HH);
        half_trans<<<(n + 255) / 256, 256>>>(W2, W2T, HH, HH);
    }

    const dim3 gH(HH / 128, BB / 128);   // (4, 512)
    const dim3 gO(1,        BB / 128);   // (1, 512)

    // 1) h0 = tanh(x @ W0 + b0)
    hnn_mma<0, 128, 4><<<gH, 256, SM128>>>(xq, W0T, b0, nullptr, nullptr, h0, nullptr, DD);
    // 2) h1 = tanh(h0 @ W1 + b1)
    hnn_mma<0, 128, 4><<<gH, 256, SM128>>>(h0, W1T, b1, nullptr, nullptr, h1, nullptr, HH);
    // 3) d2 = W3 * (1 - tanh^2(h1 @ W2 + b2))
    hnn_mma<1, 128, 4><<<gH, 256, SM128>>>(h1, W2T, b2, W3, nullptr, da, nullptr, HH);
    // 4) d1 = (d2 @ W2^T) * (1 - h1^2)
    hnn_mma<2, 128, 4><<<gH, 256, SM128>>>(da, W2q, nullptr, nullptr, h1, d1, nullptr, HH);
    // 5) d0 = (d1 @ W1^T) * (1 - h0^2)   (reuse da buffer)
    hnn_mma<2, 128, 4><<<gH, 256, SM128>>>(d1, W1q, nullptr, nullptr, h0, da, nullptr, HH);
    // 6) out = symplectic(d0 @ W0^T)
    hnn_mma<3, 64, 8><<<gO, 256, SM64>>>(da, W0q, nullptr, nullptr, nullptr, nullptr, out, HH);
}